// round 3
// baseline (speedup 1.0000x reference)
#include <cuda_runtime.h>

#define IN_DIM 256
#define OUT_DIM 128
#define MAX_NODES 100000

// Scratch for h = X @ W  (51.2 MB). __device__ global = allowed scratch.
__device__ float g_h[(size_t)MAX_NODES * OUT_DIM];

// ---------------------------------------------------------------------------
// Kernel 1: tiled fp32 GEMM  h[M,128] = X[M,256] @ W[256,128]
// BM=128, BN=128, BK=16, 256 threads, 8x8 register tile per thread.
// ---------------------------------------------------------------------------
__global__ __launch_bounds__(256) void gemm_kernel(const float* __restrict__ X,
                                                   const float* __restrict__ W,
                                                   int M) {
    __shared__ float As[16][128];   // A tile, transposed (k-major)
    __shared__ float Bs[16][128];

    const int tid = threadIdx.x;
    const int tx = tid & 15;        // 0..15 -> output col group
    const int ty = tid >> 4;        // 0..15 -> output row group
    const int rowBase = blockIdx.x * 128;

    float acc[8][8];
    #pragma unroll
    for (int i = 0; i < 8; i++)
        #pragma unroll
        for (int j = 0; j < 8; j++) acc[i][j] = 0.0f;

    for (int kt = 0; kt < IN_DIM; kt += 16) {
        // Load A tile: 128 rows x 16 cols = 512 float4, 2 per thread.
        #pragma unroll
        for (int l = 0; l < 2; l++) {
            int f = tid + l * 256;
            int r = f >> 2;            // 0..127
            int c = (f & 3) * 4;       // 0,4,8,12
            int gr = rowBase + r;
            float4 v = make_float4(0.f, 0.f, 0.f, 0.f);
            if (gr < M)
                v = *(const float4*)(X + (size_t)gr * IN_DIM + kt + c);
            As[c + 0][r] = v.x;
            As[c + 1][r] = v.y;
            As[c + 2][r] = v.z;
            As[c + 3][r] = v.w;
        }
        // Load B tile: 16 rows x 128 cols = 512 float4, 2 per thread.
        #pragma unroll
        for (int l = 0; l < 2; l++) {
            int f = tid + l * 256;
            int r = f >> 5;            // 0..15
            int c = (f & 31) * 4;      // 0..124
            float4 v = *(const float4*)(W + (size_t)(kt + r) * OUT_DIM + c);
            *(float4*)(&Bs[r][c]) = v;
        }
        __syncthreads();

        #pragma unroll
        for (int k = 0; k < 16; k++) {
            float ra[8], rb[8];
            #pragma unroll
            for (int i = 0; i < 8; i++) ra[i] = As[k][ty * 8 + i];
            #pragma unroll
            for (int j = 0; j < 8; j++) rb[j] = Bs[k][tx * 8 + j];
            #pragma unroll
            for (int i = 0; i < 8; i++)
                #pragma unroll
                for (int j = 0; j < 8; j++)
                    acc[i][j] += ra[i] * rb[j];
        }
        __syncthreads();
    }

    // Store h (float4).
    #pragma unroll
    for (int i = 0; i < 8; i++) {
        int gr = rowBase + ty * 8 + i;
        if (gr < M) {
            #pragma unroll
            for (int j = 0; j < 8; j += 4) {
                float4 v = make_float4(acc[i][j], acc[i][j + 1],
                                       acc[i][j + 2], acc[i][j + 3]);
                *(float4*)(g_h + (size_t)gr * OUT_DIM + tx * 8 + j) = v;
            }
        }
    }
}

// ---------------------------------------------------------------------------
// Kernel 2: out[n][j] = b[j]   (also un-poisons d_out)
// ---------------------------------------------------------------------------
__global__ void bias_kernel(float4* __restrict__ out, const float* __restrict__ b,
                            int total4) {
    int i = blockIdx.x * blockDim.x + threadIdx.x;
    if (i < total4) {
        int j = (i & 31) * 4;  // column offset within 128-wide row
        out[i] = make_float4(__ldg(&b[j]), __ldg(&b[j + 1]),
                             __ldg(&b[j + 2]), __ldg(&b[j + 3]));
    }
}

// ---------------------------------------------------------------------------
// Kernel 3: scatter-add. One warp per edge; lane handles 4 consecutive floats
// via a single vectorized red.global.add.v4.f32.
// out[dst] += val * h[src]
// ---------------------------------------------------------------------------
__device__ __forceinline__ void red_add_v4(float* addr, float4 v) {
    asm volatile("red.global.add.v4.f32 [%0], {%1, %2, %3, %4};"
                 :: "l"(addr), "f"(v.x), "f"(v.y), "f"(v.z), "f"(v.w)
                 : "memory");
}

__global__ __launch_bounds__(256) void scatter_kernel(const int* __restrict__ src,
                                                      const int* __restrict__ dst,
                                                      const float* __restrict__ vals,
                                                      float* __restrict__ out,
                                                      int E) {
    int gw = (int)((blockIdx.x * (long long)blockDim.x + threadIdx.x) >> 5);
    int lane = threadIdx.x & 31;
    if (gw >= E) return;

    // Uniform loads: all lanes hit the same address -> L1 broadcast.
    int s   = __ldg(&src[gw]);
    int d   = __ldg(&dst[gw]);
    float v = __ldg(&vals[gw]);

    float4 m = *(const float4*)(g_h + (size_t)s * OUT_DIM + lane * 4);
    float* op = out + (size_t)d * OUT_DIM + lane * 4;
    red_add_v4(op, make_float4(v * m.x, v * m.y, v * m.z, v * m.w));
}

// ---------------------------------------------------------------------------
extern "C" void kernel_launch(void* const* d_in, const int* in_sizes, int n_in,
                              void* d_out, int out_size) {
    const float* X     = (const float*)d_in[0];  // feature_map [N, 256]
    const int*   esrc  = (const int*)d_in[1];    // edge_src [E]
    const int*   edst  = (const int*)d_in[2];    // edge_dst [E]
    const float* evals = (const float*)d_in[3];  // edge_vals [E]
    const float* W     = (const float*)d_in[4];  // weights [256, 128]
    const float* b     = (const float*)d_in[5];  // bias [128]
    float* out = (float*)d_out;

    int M = in_sizes[0] / IN_DIM;   // N_NODES
    int E = in_sizes[1];            // N_EDGES

    // 1) h = X @ W
    gemm_kernel<<<(M + 127) / 128, 256>>>(X, W, M);

    // 2) out = b (broadcast, float4 stores)
    int total4 = M * OUT_DIM / 4;
    bias_kernel<<<(total4 + 255) / 256, 256>>>((float4*)out, b, total4);

    // 3) out[dst] += val * h[src]
    long long threads = (long long)E * 32;
    int blocks = (int)((threads + 255) / 256);
    scatter_kernel<<<blocks, 256>>>(esrc, edst, evals, out, E);
}

// round 4
// speedup vs baseline: 1.1665x; 1.1665x over previous
#include <cuda_runtime.h>

#define IN_DIM 256
#define OUT_DIM 128
#define MAX_NODES 100000

// Scratch for h = X @ W  (51.2 MB). __device__ global = allowed scratch.
__device__ float g_h[(size_t)MAX_NODES * OUT_DIM];

// ---------------------------------------------------------------------------
// Kernel 1: tiled fp32 GEMM  h[M,128] = X[M,256] @ W[256,128]
// BM=128, BN=128, BK=16, 256 threads, 8x8 register tile per thread.
// Double-buffered smem with register prefetch: load tile t+1 from global
// into registers while computing tile t, then STS + one sync per iter.
// ---------------------------------------------------------------------------
__global__ __launch_bounds__(256, 2) void gemm_kernel(const float* __restrict__ X,
                                                      const float* __restrict__ W,
                                                      int M) {
    __shared__ float As[2][16][128];   // k-major (transposed A)
    __shared__ float Bs[2][16][128];

    const int tid = threadIdx.x;
    const int tx = tid & 15;        // output col group
    const int ty = tid >> 4;        // output row group
    const int rowBase = blockIdx.x * 128;

    // Per-thread load coordinates (invariant across k-tiles).
    // A: 2 float4 per thread.  f = tid + l*256 ; r = f>>2 ; c = (f&3)*4
    const int ar0 = tid >> 2;            // l=0 row 0..63
    const int ar1 = (tid + 256) >> 2;    // l=1 row 64..127
    const int ac  = (tid & 3) * 4;       // col 0,4,8,12
    // B: 2 float4 per thread.  r = f>>5 ; c = (f&31)*4
    const int br0 = tid >> 5;            // 0..7
    const int br1 = (tid + 256) >> 5;    // 8..15
    const int bc  = (tid & 31) * 4;

    const bool aok0 = (rowBase + ar0) < M;
    const bool aok1 = (rowBase + ar1) < M;
    const float* Xp0 = X + (size_t)(rowBase + ar0) * IN_DIM + ac;
    const float* Xp1 = X + (size_t)(rowBase + ar1) * IN_DIM + ac;
    const float* Wp0 = W + (size_t)br0 * OUT_DIM + bc;
    const float* Wp1 = W + (size_t)br1 * OUT_DIM + bc;

    float acc[8][8];
    #pragma unroll
    for (int i = 0; i < 8; i++)
        #pragma unroll
        for (int j = 0; j < 8; j++) acc[i][j] = 0.0f;

    float4 a0, a1, b0, b1;

    // Prologue: load tile 0.
    a0 = aok0 ? *(const float4*)(Xp0) : make_float4(0.f, 0.f, 0.f, 0.f);
    a1 = aok1 ? *(const float4*)(Xp1) : make_float4(0.f, 0.f, 0.f, 0.f);
    b0 = *(const float4*)(Wp0);
    b1 = *(const float4*)(Wp1);

    // Store tile 0 into buffer 0.
    As[0][ac + 0][ar0] = a0.x; As[0][ac + 1][ar0] = a0.y;
    As[0][ac + 2][ar0] = a0.z; As[0][ac + 3][ar0] = a0.w;
    As[0][ac + 0][ar1] = a1.x; As[0][ac + 1][ar1] = a1.y;
    As[0][ac + 2][ar1] = a1.z; As[0][ac + 3][ar1] = a1.w;
    *(float4*)(&Bs[0][br0][bc]) = b0;
    *(float4*)(&Bs[0][br1][bc]) = b1;
    __syncthreads();

    const int NT = IN_DIM / 16;  // 16 k-tiles
    #pragma unroll 1
    for (int t = 0; t < NT; t++) {
        const int buf = t & 1;

        // Prefetch tile t+1 from global into registers.
        if (t + 1 < NT) {
            const int koff = (t + 1) * 16;
            a0 = aok0 ? *(const float4*)(Xp0 + koff) : make_float4(0.f, 0.f, 0.f, 0.f);
            a1 = aok1 ? *(const float4*)(Xp1 + koff) : make_float4(0.f, 0.f, 0.f, 0.f);
            b0 = *(const float4*)(Wp0 + (size_t)koff * OUT_DIM);
            b1 = *(const float4*)(Wp1 + (size_t)koff * OUT_DIM);
        }

        // Compute on current buffer.
        #pragma unroll
        for (int k = 0; k < 16; k++) {
            float ra[8], rb[8];
            #pragma unroll
            for (int i = 0; i < 8; i += 4)
                *(float4*)(&ra[i]) = *(const float4*)(&As[buf][k][ty * 8 + i]);
            #pragma unroll
            for (int j = 0; j < 8; j += 4)
                *(float4*)(&rb[j]) = *(const float4*)(&Bs[buf][k][tx * 8 + j]);
            #pragma unroll
            for (int i = 0; i < 8; i++)
                #pragma unroll
                for (int j = 0; j < 8; j++)
                    acc[i][j] += ra[i] * rb[j];
        }

        // Publish tile t+1 into the other buffer.
        if (t + 1 < NT) {
            const int nb = buf ^ 1;
            As[nb][ac + 0][ar0] = a0.x; As[nb][ac + 1][ar0] = a0.y;
            As[nb][ac + 2][ar0] = a0.z; As[nb][ac + 3][ar0] = a0.w;
            As[nb][ac + 0][ar1] = a1.x; As[nb][ac + 1][ar1] = a1.y;
            As[nb][ac + 2][ar1] = a1.z; As[nb][ac + 3][ar1] = a1.w;
            *(float4*)(&Bs[nb][br0][bc]) = b0;
            *(float4*)(&Bs[nb][br1][bc]) = b1;
            __syncthreads();
        }
    }

    // Store h (float4).
    #pragma unroll
    for (int i = 0; i < 8; i++) {
        int gr = rowBase + ty * 8 + i;
        if (gr < M) {
            #pragma unroll
            for (int j = 0; j < 8; j += 4) {
                float4 v = make_float4(acc[i][j], acc[i][j + 1],
                                       acc[i][j + 2], acc[i][j + 3]);
                *(float4*)(g_h + (size_t)gr * OUT_DIM + tx * 8 + j) = v;
            }
        }
    }
}

// ---------------------------------------------------------------------------
// Kernel 2: out[n][j] = b[j]   (also un-poisons d_out)
// ---------------------------------------------------------------------------
__global__ void bias_kernel(float4* __restrict__ out, const float* __restrict__ b,
                            int total4) {
    int i = blockIdx.x * blockDim.x + threadIdx.x;
    if (i < total4) {
        int j = (i & 31) * 4;  // column offset within 128-wide row
        out[i] = make_float4(__ldg(&b[j]), __ldg(&b[j + 1]),
                             __ldg(&b[j + 2]), __ldg(&b[j + 3]));
    }
}

// ---------------------------------------------------------------------------
// Kernel 3: scatter-add. One warp per TWO edges (MLP=2); lane handles 4
// consecutive floats via a single vectorized red.global.add.v4.f32.
// out[dst] += val * h[src]
// ---------------------------------------------------------------------------
__device__ __forceinline__ void red_add_v4(float* addr, float4 v) {
    asm volatile("red.global.add.v4.f32 [%0], {%1, %2, %3, %4};"
                 :: "l"(addr), "f"(v.x), "f"(v.y), "f"(v.z), "f"(v.w)
                 : "memory");
}

__global__ __launch_bounds__(256) void scatter_kernel(const int* __restrict__ src,
                                                      const int* __restrict__ dst,
                                                      const float* __restrict__ vals,
                                                      float* __restrict__ out,
                                                      int E) {
    long long gw = (blockIdx.x * (long long)blockDim.x + threadIdx.x) >> 5;
    int lane = threadIdx.x & 31;
    long long e0 = gw * 2;
    if (e0 >= E) return;
    const bool has1 = (e0 + 1) < E;

    // Uniform loads (L1 broadcast) for both edges up front.
    int   s0 = __ldg(&src[e0]);
    int   d0 = __ldg(&dst[e0]);
    float v0 = __ldg(&vals[e0]);
    int s1 = 0, d1 = 0; float v1 = 0.f;
    if (has1) {
        s1 = __ldg(&src[e0 + 1]);
        d1 = __ldg(&dst[e0 + 1]);
        v1 = __ldg(&vals[e0 + 1]);
    }

    // Both gathers outstanding before either RED.
    float4 m0 = *(const float4*)(g_h + (size_t)s0 * OUT_DIM + lane * 4);
    float4 m1 = make_float4(0.f, 0.f, 0.f, 0.f);
    if (has1)
        m1 = *(const float4*)(g_h + (size_t)s1 * OUT_DIM + lane * 4);

    red_add_v4(out + (size_t)d0 * OUT_DIM + lane * 4,
               make_float4(v0 * m0.x, v0 * m0.y, v0 * m0.z, v0 * m0.w));
    if (has1)
        red_add_v4(out + (size_t)d1 * OUT_DIM + lane * 4,
                   make_float4(v1 * m1.x, v1 * m1.y, v1 * m1.z, v1 * m1.w));
}

// ---------------------------------------------------------------------------
extern "C" void kernel_launch(void* const* d_in, const int* in_sizes, int n_in,
                              void* d_out, int out_size) {
    const float* X     = (const float*)d_in[0];  // feature_map [N, 256]
    const int*   esrc  = (const int*)d_in[1];    // edge_src [E]
    const int*   edst  = (const int*)d_in[2];    // edge_dst [E]
    const float* evals = (const float*)d_in[3];  // edge_vals [E]
    const float* W     = (const float*)d_in[4];  // weights [256, 128]
    const float* b     = (const float*)d_in[5];  // bias [128]
    float* out = (float*)d_out;

    int M = in_sizes[0] / IN_DIM;   // N_NODES
    int E = in_sizes[1];            // N_EDGES

    // 1) h = X @ W
    gemm_kernel<<<(M + 127) / 128, 256>>>(X, W, M);

    // 2) out = b (broadcast, float4 stores)
    int total4 = M * OUT_DIM / 4;
    bias_kernel<<<(total4 + 255) / 256, 256>>>((float4*)out, b, total4);

    // 3) out[dst] += val * h[src]   (2 edges per warp)
    long long warps = ((long long)E + 1) / 2;
    long long threads = warps * 32;
    int blocks = (int)((threads + 255) / 256);
    scatter_kernel<<<blocks, 256>>>(esrc, edst, evals, out, E);
}

// round 6
// speedup vs baseline: 1.1924x; 1.0223x over previous
#include <cuda_runtime.h>

#define IN_DIM 256
#define OUT_DIM 128
#define MAX_NODES 100000

// Scratch for h = X @ W  (51.2 MB). __device__ global = allowed scratch.
__device__ float g_h[(size_t)MAX_NODES * OUT_DIM];

// ---------------------------------------------------------------------------
// Kernel 1: tiled fp32 GEMM  h[M,128] = X[M,256] @ W[256,128]
// BM=128, BN=128, BK=16, 256 threads, 8x8 register tile per thread.
// Columns are split into two chunks (tx*4 and 64+tx*4) so every Bs LDS.128
// phase reads 128 contiguous bytes -> conflict-free shared loads.
// Double-buffered smem with register prefetch.
// ---------------------------------------------------------------------------
__global__ __launch_bounds__(256, 2) void gemm_kernel(const float* __restrict__ X,
                                                      const float* __restrict__ W,
                                                      int M) {
    __shared__ float As[2][16][128];   // k-major (transposed A)
    __shared__ float Bs[2][16][128];

    const int tid = threadIdx.x;
    const int tx = tid & 15;        // output col group (chunked)
    const int ty = tid >> 4;        // output row group
    const int rowBase = blockIdx.x * 128;

    // Per-thread load coordinates (invariant across k-tiles).
    const int ar0 = tid >> 2;            // A rows 0..63
    const int ar1 = (tid + 256) >> 2;    // A rows 64..127
    const int ac  = (tid & 3) * 4;       // A col 0,4,8,12
    const int br0 = tid >> 5;            // B rows 0..7
    const int br1 = (tid + 256) >> 5;    // B rows 8..15
    const int bc  = (tid & 31) * 4;

    const bool aok0 = (rowBase + ar0) < M;
    const bool aok1 = (rowBase + ar1) < M;
    const float* Xp0 = X + (size_t)(rowBase + ar0) * IN_DIM + ac;
    const float* Xp1 = X + (size_t)(rowBase + ar1) * IN_DIM + ac;
    const float* Wp0 = W + (size_t)br0 * OUT_DIM + bc;
    const float* Wp1 = W + (size_t)br1 * OUT_DIM + bc;

    float acc[8][8];   // [row i][j: 0-3 = cols tx*4.., 4-7 = cols 64+tx*4..]
    #pragma unroll
    for (int i = 0; i < 8; i++)
        #pragma unroll
        for (int j = 0; j < 8; j++) acc[i][j] = 0.0f;

    float4 a0, a1, b0, b1;

    // Prologue: load tile 0.
    a0 = aok0 ? *(const float4*)(Xp0) : make_float4(0.f, 0.f, 0.f, 0.f);
    a1 = aok1 ? *(const float4*)(Xp1) : make_float4(0.f, 0.f, 0.f, 0.f);
    b0 = *(const float4*)(Wp0);
    b1 = *(const float4*)(Wp1);

    As[0][ac + 0][ar0] = a0.x; As[0][ac + 1][ar0] = a0.y;
    As[0][ac + 2][ar0] = a0.z; As[0][ac + 3][ar0] = a0.w;
    As[0][ac + 0][ar1] = a1.x; As[0][ac + 1][ar1] = a1.y;
    As[0][ac + 2][ar1] = a1.z; As[0][ac + 3][ar1] = a1.w;
    *(float4*)(&Bs[0][br0][bc]) = b0;
    *(float4*)(&Bs[0][br1][bc]) = b1;
    __syncthreads();

    const int NT = IN_DIM / 16;  // 16 k-tiles
    #pragma unroll 1
    for (int t = 0; t < NT; t++) {
        const int buf = t & 1;

        // Prefetch tile t+1 from global into registers.
        if (t + 1 < NT) {
            const int koff = (t + 1) * 16;
            a0 = aok0 ? *(const float4*)(Xp0 + koff) : make_float4(0.f, 0.f, 0.f, 0.f);
            a1 = aok1 ? *(const float4*)(Xp1 + koff) : make_float4(0.f, 0.f, 0.f, 0.f);
            b0 = *(const float4*)(Wp0 + (size_t)koff * OUT_DIM);
            b1 = *(const float4*)(Wp1 + (size_t)koff * OUT_DIM);
        }

        // Compute on current buffer.
        #pragma unroll
        for (int k = 0; k < 16; k++) {
            float ra[8], rb[8];
            #pragma unroll
            for (int i = 0; i < 8; i += 4)
                *(float4*)(&ra[i]) = *(const float4*)(&As[buf][k][ty * 8 + i]);
            // Conflict-free Bs reads: each phase covers 128 contiguous bytes.
            *(float4*)(&rb[0]) = *(const float4*)(&Bs[buf][k][tx * 4]);
            *(float4*)(&rb[4]) = *(const float4*)(&Bs[buf][k][64 + tx * 4]);
            #pragma unroll
            for (int i = 0; i < 8; i++)
                #pragma unroll
                for (int j = 0; j < 8; j++)
                    acc[i][j] += ra[i] * rb[j];
        }

        // Publish tile t+1 into the other buffer.
        if (t + 1 < NT) {
            const int nb = buf ^ 1;
            As[nb][ac + 0][ar0] = a0.x; As[nb][ac + 1][ar0] = a0.y;
            As[nb][ac + 2][ar0] = a0.z; As[nb][ac + 3][ar0] = a0.w;
            As[nb][ac + 0][ar1] = a1.x; As[nb][ac + 1][ar1] = a1.y;
            As[nb][ac + 2][ar1] = a1.z; As[nb][ac + 3][ar1] = a1.w;
            *(float4*)(&Bs[nb][br0][bc]) = b0;
            *(float4*)(&Bs[nb][br1][bc]) = b1;
            __syncthreads();
        }
    }

    // Store h (two float4 chunks per row).
    #pragma unroll
    for (int i = 0; i < 8; i++) {
        int gr = rowBase + ty * 8 + i;
        if (gr < M) {
            *(float4*)(g_h + (size_t)gr * OUT_DIM + tx * 4) =
                make_float4(acc[i][0], acc[i][1], acc[i][2], acc[i][3]);
            *(float4*)(g_h + (size_t)gr * OUT_DIM + 64 + tx * 4) =
                make_float4(acc[i][4], acc[i][5], acc[i][6], acc[i][7]);
        }
    }
}

// ---------------------------------------------------------------------------
// Kernel 2: out[n][j] = b[j]   (also un-poisons d_out)
// ---------------------------------------------------------------------------
__global__ void bias_kernel(float4* __restrict__ out, const float* __restrict__ b,
                            int total4) {
    int i = blockIdx.x * blockDim.x + threadIdx.x;
    if (i < total4) {
        int j = (i & 31) * 4;  // column offset within 128-wide row
        out[i] = make_float4(__ldg(&b[j]), __ldg(&b[j + 1]),
                             __ldg(&b[j + 2]), __ldg(&b[j + 3]));
    }
}

// ---------------------------------------------------------------------------
// Kernel 3: scatter-add. One warp per FOUR edges (MLP=4); lane handles 4
// consecutive floats via a single vectorized red.global.add.v4.f32.
// out[dst] += val * h[src]
// ---------------------------------------------------------------------------
__device__ __forceinline__ void red_add_v4(float* addr, float4 v) {
    asm volatile("red.global.add.v4.f32 [%0], {%1, %2, %3, %4};"
                 :: "l"(addr), "f"(v.x), "f"(v.y), "f"(v.z), "f"(v.w)
                 : "memory");
}

#define EPW 4   // edges per warp

__global__ __launch_bounds__(256) void scatter_kernel(const int* __restrict__ src,
                                                      const int* __restrict__ dst,
                                                      const float* __restrict__ vals,
                                                      float* __restrict__ out,
                                                      int E) {
    long long gw = (blockIdx.x * (long long)blockDim.x + threadIdx.x) >> 5;
    const int lane = threadIdx.x & 31;
    long long base = gw * EPW;
    if (base >= E) return;

    int   s[EPW], d[EPW];
    float v[EPW];
    float4 m[EPW];

    // Uniform scalar loads for all edges up front (L1 broadcast).
    #pragma unroll
    for (int i = 0; i < EPW; i++) {
        long long e = base + i;
        if (e < E) {
            s[i] = __ldg(&src[e]);
            d[i] = __ldg(&dst[e]);
            v[i] = __ldg(&vals[e]);
        } else {
            s[i] = 0; d[i] = -1; v[i] = 0.f;
        }
    }

    // All gathers outstanding before any RED.
    #pragma unroll
    for (int i = 0; i < EPW; i++)
        m[i] = *(const float4*)(g_h + (size_t)s[i] * OUT_DIM + lane * 4);

    #pragma unroll
    for (int i = 0; i < EPW; i++) {
        if (d[i] >= 0)
            red_add_v4(out + (size_t)d[i] * OUT_DIM + lane * 4,
                       make_float4(v[i] * m[i].x, v[i] * m[i].y,
                                   v[i] * m[i].z, v[i] * m[i].w));
    }
}

// ---------------------------------------------------------------------------
extern "C" void kernel_launch(void* const* d_in, const int* in_sizes, int n_in,
                              void* d_out, int out_size) {
    const float* X     = (const float*)d_in[0];  // feature_map [N, 256]
    const int*   esrc  = (const int*)d_in[1];    // edge_src [E]
    const int*   edst  = (const int*)d_in[2];    // edge_dst [E]
    const float* evals = (const float*)d_in[3];  // edge_vals [E]
    const float* W     = (const float*)d_in[4];  // weights [256, 128]
    const float* b     = (const float*)d_in[5];  // bias [128]
    float* out = (float*)d_out;

    int M = in_sizes[0] / IN_DIM;   // N_NODES
    int E = in_sizes[1];            // N_EDGES

    // 1) h = X @ W
    gemm_kernel<<<(M + 127) / 128, 256>>>(X, W, M);

    // 2) out = b (broadcast, float4 stores)
    int total4 = M * OUT_DIM / 4;
    bias_kernel<<<(total4 + 255) / 256, 256>>>((float4*)out, b, total4);

    // 3) out[dst] += val * h[src]   (4 edges per warp)
    long long warps = ((long long)E + EPW - 1) / EPW;
    long long threads = warps * 32;
    int blocks = (int)((threads + 255) / 256);
    scatter_kernel<<<blocks, 256>>>(esrc, edst, evals, out, E);
}

// round 7
// speedup vs baseline: 1.2329x; 1.0340x over previous
#include <cuda_runtime.h>

#define IN_DIM 256
#define OUT_DIM 128
#define MAX_NODES 100000

// Scratch for h = X @ W  (51.2 MB). __device__ global = allowed scratch.
__device__ float g_h[(size_t)MAX_NODES * OUT_DIM];

// ---- packed dual-fp32 helpers (Blackwell FFMA2; PTX-only path) -------------
__device__ __forceinline__ unsigned long long pack2(float lo, float hi) {
    unsigned long long r;
    asm("mov.b64 %0, {%1, %2};" : "=l"(r) : "f"(lo), "f"(hi));
    return r;
}
__device__ __forceinline__ void unpack2(unsigned long long p, float& lo, float& hi) {
    asm("mov.b64 {%0, %1}, %2;" : "=f"(lo), "=f"(hi) : "l"(p));
}
__device__ __forceinline__ void fma2(unsigned long long& acc,
                                     unsigned long long a, unsigned long long b) {
    asm("fma.rn.f32x2 %0, %1, %2, %0;" : "+l"(acc) : "l"(a), "l"(b));
}

// ---------------------------------------------------------------------------
// Kernel 1: tiled fp32 GEMM  h[M,128] = X[M,256] @ W[256,128]
// BM=128, BN=128, BK=16, 256 threads, 8x8 register tile per thread.
// Inner product uses fma.rn.f32x2 (FFMA2): 32 packed FMA per k instead of
// 64 scalar FFMA -> halves the fma-pipe issue slots (the measured floor).
// Conflict-free Bs reads (column chunks tx*4 and 64+tx*4); double-buffered.
// ---------------------------------------------------------------------------
__global__ __launch_bounds__(256, 2) void gemm_kernel(const float* __restrict__ X,
                                                      const float* __restrict__ W,
                                                      int M) {
    __shared__ float As[2][16][128];   // k-major (transposed A)
    __shared__ float Bs[2][16][128];

    const int tid = threadIdx.x;
    const int tx = tid & 15;        // output col group (chunked)
    const int ty = tid >> 4;        // output row group
    const int rowBase = blockIdx.x * 128;

    const int ar0 = tid >> 2;            // A rows 0..63
    const int ar1 = (tid + 256) >> 2;    // A rows 64..127
    const int ac  = (tid & 3) * 4;       // A col 0,4,8,12
    const int br0 = tid >> 5;            // B rows 0..7
    const int br1 = (tid + 256) >> 5;    // B rows 8..15
    const int bc  = (tid & 31) * 4;

    const bool aok0 = (rowBase + ar0) < M;
    const bool aok1 = (rowBase + ar1) < M;
    const float* Xp0 = X + (size_t)(rowBase + ar0) * IN_DIM + ac;
    const float* Xp1 = X + (size_t)(rowBase + ar1) * IN_DIM + ac;
    const float* Wp0 = W + (size_t)br0 * OUT_DIM + bc;
    const float* Wp1 = W + (size_t)br1 * OUT_DIM + bc;

    // acc2[i][j] = packed pair of output cols; j 0-1 -> chunk tx*4, 2-3 -> 64+tx*4
    unsigned long long acc2[8][4];
    #pragma unroll
    for (int i = 0; i < 8; i++)
        #pragma unroll
        for (int j = 0; j < 4; j++) acc2[i][j] = 0ull;

    float4 a0, a1, b0, b1;

    // Prologue: load tile 0.
    a0 = aok0 ? *(const float4*)(Xp0) : make_float4(0.f, 0.f, 0.f, 0.f);
    a1 = aok1 ? *(const float4*)(Xp1) : make_float4(0.f, 0.f, 0.f, 0.f);
    b0 = *(const float4*)(Wp0);
    b1 = *(const float4*)(Wp1);

    As[0][ac + 0][ar0] = a0.x; As[0][ac + 1][ar0] = a0.y;
    As[0][ac + 2][ar0] = a0.z; As[0][ac + 3][ar0] = a0.w;
    As[0][ac + 0][ar1] = a1.x; As[0][ac + 1][ar1] = a1.y;
    As[0][ac + 2][ar1] = a1.z; As[0][ac + 3][ar1] = a1.w;
    *(float4*)(&Bs[0][br0][bc]) = b0;
    *(float4*)(&Bs[0][br1][bc]) = b1;
    __syncthreads();

    const int NT = IN_DIM / 16;  // 16 k-tiles
    #pragma unroll 1
    for (int t = 0; t < NT; t++) {
        const int buf = t & 1;

        // Prefetch tile t+1 from global into registers.
        if (t + 1 < NT) {
            const int koff = (t + 1) * 16;
            a0 = aok0 ? *(const float4*)(Xp0 + koff) : make_float4(0.f, 0.f, 0.f, 0.f);
            a1 = aok1 ? *(const float4*)(Xp1 + koff) : make_float4(0.f, 0.f, 0.f, 0.f);
            b0 = *(const float4*)(Wp0 + (size_t)koff * OUT_DIM);
            b1 = *(const float4*)(Wp1 + (size_t)koff * OUT_DIM);
        }

        // Compute on current buffer (packed FFMA2).
        #pragma unroll
        for (int k = 0; k < 16; k++) {
            float ra[8], rb[8];
            #pragma unroll
            for (int i = 0; i < 8; i += 4)
                *(float4*)(&ra[i]) = *(const float4*)(&As[buf][k][ty * 8 + i]);
            *(float4*)(&rb[0]) = *(const float4*)(&Bs[buf][k][tx * 4]);
            *(float4*)(&rb[4]) = *(const float4*)(&Bs[buf][k][64 + tx * 4]);

            unsigned long long rbp[4], rap[8];
            #pragma unroll
            for (int j = 0; j < 4; j++) rbp[j] = pack2(rb[2 * j], rb[2 * j + 1]);
            #pragma unroll
            for (int i = 0; i < 8; i++) rap[i] = pack2(ra[i], ra[i]);

            #pragma unroll
            for (int i = 0; i < 8; i++)
                #pragma unroll
                for (int j = 0; j < 4; j++)
                    fma2(acc2[i][j], rap[i], rbp[j]);
        }

        // Publish tile t+1 into the other buffer.
        if (t + 1 < NT) {
            const int nb = buf ^ 1;
            As[nb][ac + 0][ar0] = a0.x; As[nb][ac + 1][ar0] = a0.y;
            As[nb][ac + 2][ar0] = a0.z; As[nb][ac + 3][ar0] = a0.w;
            As[nb][ac + 0][ar1] = a1.x; As[nb][ac + 1][ar1] = a1.y;
            As[nb][ac + 2][ar1] = a1.z; As[nb][ac + 3][ar1] = a1.w;
            *(float4*)(&Bs[nb][br0][bc]) = b0;
            *(float4*)(&Bs[nb][br1][bc]) = b1;
            __syncthreads();
        }
    }

    // Store h (two float4 chunks per row).
    #pragma unroll
    for (int i = 0; i < 8; i++) {
        int gr = rowBase + ty * 8 + i;
        if (gr < M) {
            float4 c0, c1;
            unpack2(acc2[i][0], c0.x, c0.y);
            unpack2(acc2[i][1], c0.z, c0.w);
            unpack2(acc2[i][2], c1.x, c1.y);
            unpack2(acc2[i][3], c1.z, c1.w);
            *(float4*)(g_h + (size_t)gr * OUT_DIM + tx * 4) = c0;
            *(float4*)(g_h + (size_t)gr * OUT_DIM + 64 + tx * 4) = c1;
        }
    }
}

// ---------------------------------------------------------------------------
// Kernel 2: out[n][j] = b[j]   (also un-poisons d_out)
// ---------------------------------------------------------------------------
__global__ void bias_kernel(float4* __restrict__ out, const float* __restrict__ b,
                            int total4) {
    int i = blockIdx.x * blockDim.x + threadIdx.x;
    if (i < total4) {
        int j = (i & 31) * 4;  // column offset within 128-wide row
        out[i] = make_float4(__ldg(&b[j]), __ldg(&b[j + 1]),
                             __ldg(&b[j + 2]), __ldg(&b[j + 3]));
    }
}

// ---------------------------------------------------------------------------
// Kernel 3: scatter-add. One warp per FOUR edges; lane handles 4 consecutive
// floats via a single vectorized red.global.add.v4.f32.
// out[dst] += val * h[src]
// ---------------------------------------------------------------------------
__device__ __forceinline__ void red_add_v4(float* addr, float4 v) {
    asm volatile("red.global.add.v4.f32 [%0], {%1, %2, %3, %4};"
                 :: "l"(addr), "f"(v.x), "f"(v.y), "f"(v.z), "f"(v.w)
                 : "memory");
}

#define EPW 4   // edges per warp

__global__ __launch_bounds__(256) void scatter_kernel(const int* __restrict__ src,
                                                      const int* __restrict__ dst,
                                                      const float* __restrict__ vals,
                                                      float* __restrict__ out,
                                                      int E) {
    long long gw = (blockIdx.x * (long long)blockDim.x + threadIdx.x) >> 5;
    const int lane = threadIdx.x & 31;
    long long base = gw * EPW;
    if (base >= E) return;

    int   s[EPW], d[EPW];
    float v[EPW];
    float4 m[EPW];

    #pragma unroll
    for (int i = 0; i < EPW; i++) {
        long long e = base + i;
        if (e < E) {
            s[i] = __ldg(&src[e]);
            d[i] = __ldg(&dst[e]);
            v[i] = __ldg(&vals[e]);
        } else {
            s[i] = 0; d[i] = -1; v[i] = 0.f;
        }
    }

    #pragma unroll
    for (int i = 0; i < EPW; i++)
        m[i] = *(const float4*)(g_h + (size_t)s[i] * OUT_DIM + lane * 4);

    #pragma unroll
    for (int i = 0; i < EPW; i++) {
        if (d[i] >= 0)
            red_add_v4(out + (size_t)d[i] * OUT_DIM + lane * 4,
                       make_float4(v[i] * m[i].x, v[i] * m[i].y,
                                   v[i] * m[i].z, v[i] * m[i].w));
    }
}

// ---------------------------------------------------------------------------
extern "C" void kernel_launch(void* const* d_in, const int* in_sizes, int n_in,
                              void* d_out, int out_size) {
    const float* X     = (const float*)d_in[0];  // feature_map [N, 256]
    const int*   esrc  = (const int*)d_in[1];    // edge_src [E]
    const int*   edst  = (const int*)d_in[2];    // edge_dst [E]
    const float* evals = (const float*)d_in[3];  // edge_vals [E]
    const float* W     = (const float*)d_in[4];  // weights [256, 128]
    const float* b     = (const float*)d_in[5];  // bias [128]
    float* out = (float*)d_out;

    int M = in_sizes[0] / IN_DIM;   // N_NODES
    int E = in_sizes[1];            // N_EDGES

    // 1) h = X @ W
    gemm_kernel<<<(M + 127) / 128, 256>>>(X, W, M);

    // 2) out = b (broadcast, float4 stores)
    int total4 = M * OUT_DIM / 4;
    bias_kernel<<<(total4 + 255) / 256, 256>>>((float4*)out, b, total4);

    // 3) out[dst] += val * h[src]   (4 edges per warp)
    long long warps = ((long long)E + EPW - 1) / EPW;
    long long threads = warps * 32;
    int blocks = (int)((threads + 255) / 256);
    scatter_kernel<<<blocks, 256>>>(esrc, edst, evals, out, E);
}

// round 8
// speedup vs baseline: 1.2402x; 1.0059x over previous
#include <cuda_runtime.h>
#include <cuda_fp16.h>

#define IN_DIM 256
#define OUT_DIM 128
#define MAX_NODES 100000

// Scratch for h = X @ W stored as fp16 (25.6 MB): halves the scatter-gather
// LTS traffic. fp16 quantization (~2.4e-4 RMS rel) is 3x under the 1e-3 gate.
__device__ __half g_h[(size_t)MAX_NODES * OUT_DIM];

// ---- packed dual-fp32 helpers (Blackwell FFMA2; PTX-only path) -------------
__device__ __forceinline__ unsigned long long pack2(float lo, float hi) {
    unsigned long long r;
    asm("mov.b64 %0, {%1, %2};" : "=l"(r) : "f"(lo), "f"(hi));
    return r;
}
__device__ __forceinline__ void unpack2(unsigned long long p, float& lo, float& hi) {
    asm("mov.b64 {%0, %1}, %2;" : "=f"(lo), "=f"(hi) : "l"(p));
}
__device__ __forceinline__ void fma2(unsigned long long& acc,
                                     unsigned long long a, unsigned long long b) {
    asm("fma.rn.f32x2 %0, %1, %2, %0;" : "+l"(acc) : "l"(a), "l"(b));
}

// ---------------------------------------------------------------------------
// Kernel 1: tiled fp32 GEMM  h[M,128] = X[M,256] @ W[256,128]
// BM=128, BN=128, BK=16, 256 threads, 8x8 register tile, FFMA2 inner product.
// Conflict-free Bs reads (column chunks tx*4 and 64+tx*4); double-buffered.
// Epilogue converts to fp16 and stores to g_h.
// ---------------------------------------------------------------------------
__global__ __launch_bounds__(256, 2) void gemm_kernel(const float* __restrict__ X,
                                                      const float* __restrict__ W,
                                                      int M) {
    __shared__ float As[2][16][128];   // k-major (transposed A)
    __shared__ float Bs[2][16][128];

    const int tid = threadIdx.x;
    const int tx = tid & 15;        // output col group (chunked)
    const int ty = tid >> 4;        // output row group
    const int rowBase = blockIdx.x * 128;

    const int ar0 = tid >> 2;            // A rows 0..63
    const int ar1 = (tid + 256) >> 2;    // A rows 64..127
    const int ac  = (tid & 3) * 4;       // A col 0,4,8,12
    const int br0 = tid >> 5;            // B rows 0..7
    const int br1 = (tid + 256) >> 5;    // B rows 8..15
    const int bc  = (tid & 31) * 4;

    const bool aok0 = (rowBase + ar0) < M;
    const bool aok1 = (rowBase + ar1) < M;
    const float* Xp0 = X + (size_t)(rowBase + ar0) * IN_DIM + ac;
    const float* Xp1 = X + (size_t)(rowBase + ar1) * IN_DIM + ac;
    const float* Wp0 = W + (size_t)br0 * OUT_DIM + bc;
    const float* Wp1 = W + (size_t)br1 * OUT_DIM + bc;

    unsigned long long acc2[8][4];
    #pragma unroll
    for (int i = 0; i < 8; i++)
        #pragma unroll
        for (int j = 0; j < 4; j++) acc2[i][j] = 0ull;

    float4 a0, a1, b0, b1;

    // Prologue: load tile 0.
    a0 = aok0 ? *(const float4*)(Xp0) : make_float4(0.f, 0.f, 0.f, 0.f);
    a1 = aok1 ? *(const float4*)(Xp1) : make_float4(0.f, 0.f, 0.f, 0.f);
    b0 = *(const float4*)(Wp0);
    b1 = *(const float4*)(Wp1);

    As[0][ac + 0][ar0] = a0.x; As[0][ac + 1][ar0] = a0.y;
    As[0][ac + 2][ar0] = a0.z; As[0][ac + 3][ar0] = a0.w;
    As[0][ac + 0][ar1] = a1.x; As[0][ac + 1][ar1] = a1.y;
    As[0][ac + 2][ar1] = a1.z; As[0][ac + 3][ar1] = a1.w;
    *(float4*)(&Bs[0][br0][bc]) = b0;
    *(float4*)(&Bs[0][br1][bc]) = b1;
    __syncthreads();

    const int NT = IN_DIM / 16;  // 16 k-tiles
    #pragma unroll 1
    for (int t = 0; t < NT; t++) {
        const int buf = t & 1;

        if (t + 1 < NT) {
            const int koff = (t + 1) * 16;
            a0 = aok0 ? *(const float4*)(Xp0 + koff) : make_float4(0.f, 0.f, 0.f, 0.f);
            a1 = aok1 ? *(const float4*)(Xp1 + koff) : make_float4(0.f, 0.f, 0.f, 0.f);
            b0 = *(const float4*)(Wp0 + (size_t)koff * OUT_DIM);
            b1 = *(const float4*)(Wp1 + (size_t)koff * OUT_DIM);
        }

        #pragma unroll
        for (int k = 0; k < 16; k++) {
            float ra[8], rb[8];
            #pragma unroll
            for (int i = 0; i < 8; i += 4)
                *(float4*)(&ra[i]) = *(const float4*)(&As[buf][k][ty * 8 + i]);
            *(float4*)(&rb[0]) = *(const float4*)(&Bs[buf][k][tx * 4]);
            *(float4*)(&rb[4]) = *(const float4*)(&Bs[buf][k][64 + tx * 4]);

            unsigned long long rbp[4], rap[8];
            #pragma unroll
            for (int j = 0; j < 4; j++) rbp[j] = pack2(rb[2 * j], rb[2 * j + 1]);
            #pragma unroll
            for (int i = 0; i < 8; i++) rap[i] = pack2(ra[i], ra[i]);

            #pragma unroll
            for (int i = 0; i < 8; i++)
                #pragma unroll
                for (int j = 0; j < 4; j++)
                    fma2(acc2[i][j], rap[i], rbp[j]);
        }

        if (t + 1 < NT) {
            const int nb = buf ^ 1;
            As[nb][ac + 0][ar0] = a0.x; As[nb][ac + 1][ar0] = a0.y;
            As[nb][ac + 2][ar0] = a0.z; As[nb][ac + 3][ar0] = a0.w;
            As[nb][ac + 0][ar1] = a1.x; As[nb][ac + 1][ar1] = a1.y;
            As[nb][ac + 2][ar1] = a1.z; As[nb][ac + 3][ar1] = a1.w;
            *(float4*)(&Bs[nb][br0][bc]) = b0;
            *(float4*)(&Bs[nb][br1][bc]) = b1;
            __syncthreads();
        }
    }

    // Store h as fp16 (two 8-byte chunks per row).
    #pragma unroll
    for (int i = 0; i < 8; i++) {
        int gr = rowBase + ty * 8 + i;
        if (gr < M) {
            float4 c0, c1;
            unpack2(acc2[i][0], c0.x, c0.y);
            unpack2(acc2[i][1], c0.z, c0.w);
            unpack2(acc2[i][2], c1.x, c1.y);
            unpack2(acc2[i][3], c1.z, c1.w);
            __half2 h00 = __floats2half2_rn(c0.x, c0.y);
            __half2 h01 = __floats2half2_rn(c0.z, c0.w);
            __half2 h10 = __floats2half2_rn(c1.x, c1.y);
            __half2 h11 = __floats2half2_rn(c1.z, c1.w);
            __half* row = g_h + (size_t)gr * OUT_DIM;
            *(__half2*)(row + tx * 4 + 0) = h00;
            *(__half2*)(row + tx * 4 + 2) = h01;
            *(__half2*)(row + 64 + tx * 4 + 0) = h10;
            *(__half2*)(row + 64 + tx * 4 + 2) = h11;
        }
    }
}

// ---------------------------------------------------------------------------
// Kernel 2: out[n][j] = b[j]   (also un-poisons d_out)
// ---------------------------------------------------------------------------
__global__ void bias_kernel(float4* __restrict__ out, const float* __restrict__ b,
                            int total4) {
    int i = blockIdx.x * blockDim.x + threadIdx.x;
    if (i < total4) {
        int j = (i & 31) * 4;  // column offset within 128-wide row
        out[i] = make_float4(__ldg(&b[j]), __ldg(&b[j + 1]),
                             __ldg(&b[j + 2]), __ldg(&b[j + 3]));
    }
}

// ---------------------------------------------------------------------------
// Kernel 3: scatter-add. One warp per FOUR edges; lane handles 4 consecutive
// floats. Gather is fp16 (8 B/lane), RED is fp32 v4 (16 B/lane).
// out[dst] += val * h[src]
// ---------------------------------------------------------------------------
__device__ __forceinline__ void red_add_v4(float* addr, float4 v) {
    asm volatile("red.global.add.v4.f32 [%0], {%1, %2, %3, %4};"
                 :: "l"(addr), "f"(v.x), "f"(v.y), "f"(v.z), "f"(v.w)
                 : "memory");
}

#define EPW 4   // edges per warp

__global__ __launch_bounds__(256) void scatter_kernel(const int* __restrict__ src,
                                                      const int* __restrict__ dst,
                                                      const float* __restrict__ vals,
                                                      float* __restrict__ out,
                                                      int E) {
    long long gw = (blockIdx.x * (long long)blockDim.x + threadIdx.x) >> 5;
    const int lane = threadIdx.x & 31;
    long long base = gw * EPW;
    if (base >= E) return;

    int   s[EPW], d[EPW];
    float v[EPW];
    uint2 m[EPW];   // 4 halves per lane

    #pragma unroll
    for (int i = 0; i < EPW; i++) {
        long long e = base + i;
        if (e < E) {
            s[i] = __ldg(&src[e]);
            d[i] = __ldg(&dst[e]);
            v[i] = __ldg(&vals[e]);
        } else {
            s[i] = 0; d[i] = -1; v[i] = 0.f;
        }
    }

    // All gathers outstanding before any RED.
    #pragma unroll
    for (int i = 0; i < EPW; i++)
        m[i] = *(const uint2*)(g_h + (size_t)s[i] * OUT_DIM + lane * 4);

    #pragma unroll
    for (int i = 0; i < EPW; i++) {
        if (d[i] >= 0) {
            float2 p0 = __half22float2(*(const __half2*)&m[i].x);
            float2 p1 = __half22float2(*(const __half2*)&m[i].y);
            red_add_v4(out + (size_t)d[i] * OUT_DIM + lane * 4,
                       make_float4(v[i] * p0.x, v[i] * p0.y,
                                   v[i] * p1.x, v[i] * p1.y));
        }
    }
}

// ---------------------------------------------------------------------------
extern "C" void kernel_launch(void* const* d_in, const int* in_sizes, int n_in,
                              void* d_out, int out_size) {
    const float* X     = (const float*)d_in[0];  // feature_map [N, 256]
    const int*   esrc  = (const int*)d_in[1];    // edge_src [E]
    const int*   edst  = (const int*)d_in[2];    // edge_dst [E]
    const float* evals = (const float*)d_in[3];  // edge_vals [E]
    const float* W     = (const float*)d_in[4];  // weights [256, 128]
    const float* b     = (const float*)d_in[5];  // bias [128]
    float* out = (float*)d_out;

    int M = in_sizes[0] / IN_DIM;   // N_NODES
    int E = in_sizes[1];            // N_EDGES

    // 1) h = X @ W  (fp16 output)
    gemm_kernel<<<(M + 127) / 128, 256>>>(X, W, M);

    // 2) out = b (broadcast, float4 stores)
    int total4 = M * OUT_DIM / 4;
    bias_kernel<<<(total4 + 255) / 256, 256>>>((float4*)out, b, total4);

    // 3) out[dst] += val * h[src]   (4 edges per warp)
    long long warps = ((long long)E + EPW - 1) / EPW;
    long long threads = warps * 32;
    int blocks = (int)((threads + 255) / 256);
    scatter_kernel<<<blocks, 256>>>(esrc, edst, evals, out, E);
}